// round 15
// baseline (speedup 1.0000x reference)
#include <cuda_runtime.h>
#include <cuda_bf16.h>
#include <cuda_fp16.h>

#define HH 1024
#define WW 2048
#define HWSZ (HH * WW)
#define NC 19
#define RAD 16
#define INV_LOG19 0.3396224f      // 1 / ln(19)
#define LOG2_TO_19 0.23541016f    // ln(2) / ln(19)

// -------- scratch (device globals: allocation-free per harness rules) -------
// packed per-pixel record: bits[16:21) = argmax class, bits[0:16) = fp16 wpe
__device__ unsigned g_packed[HWSZ];

// ============================================================================
// Pass A: 2 pixels/thread via float2; 4-chain argmax + 2-chain S/T sums
// ============================================================================
__global__ __launch_bounds__(256) void passA(const float2* __restrict__ logit2,
                                             const float* __restrict__ cw) {
    int i = blockIdx.x * blockDim.x + threadIdx.x;   // pair index
    if (i >= HWSZ / 2) return;

    float2 v[NC];
#pragma unroll
    for (int c = 0; c < NC; c++) v[c] = logit2[c * (HWSZ / 2) + i];

    unsigned outw[2];
#pragma unroll
    for (int l = 0; l < 2; l++) {
        float x[NC];
#pragma unroll
        for (int c = 0; c < NC; c++) x[c] = l ? v[c].y : v[c].x;

        // 4-chain argmax; tie-break = lowest class (first occurrence)
        float m0 = x[0], m1 = x[5], m2 = x[10], m3 = x[15];
        int   a0 = 0,    a1 = 5,    a2 = 10,    a3 = 15;
#pragma unroll
        for (int c = 1; c < 5; c++)   if (x[c] > m0) { m0 = x[c]; a0 = c; }
#pragma unroll
        for (int c = 6; c < 10; c++)  if (x[c] > m1) { m1 = x[c]; a1 = c; }
#pragma unroll
        for (int c = 11; c < 15; c++) if (x[c] > m2) { m2 = x[c]; a2 = c; }
#pragma unroll
        for (int c = 16; c < 19; c++) if (x[c] > m3) { m3 = x[c]; a3 = c; }
        if (m1 > m0) { m0 = m1; a0 = a1; }     // strict >: lower idx keeps tie
        if (m3 > m2) { m2 = m3; a2 = a3; }
        if (m2 > m0) { m0 = m2; a0 = a2; }
        float m = m0;
        int am = a0;

        // 2-chain exp sums
        float S0 = 0.f, S1 = 0.f, T0 = 0.f, T1 = 0.f;
#pragma unroll
        for (int c = 0; c < NC; c += 2) {
            float d = x[c] - m;
            float e = __expf(d);
            S0 += e; T0 += e * d;
        }
#pragma unroll
        for (int c = 1; c < NC; c += 2) {
            float d = x[c] - m;
            float e = __expf(d);
            S1 += e; T1 += e * d;
        }
        float S = S0 + S1, T = T0 + T1;
        float ent = __logf(S) - T * __frcp_rn(S);
        float wpe = ent * cw[am] * INV_LOG19;

        outw[l] = ((unsigned)am << 16)
                | (unsigned)__half_as_ushort(__float2half_rn(wpe));
    }
    *(uint2*)(g_packed + 2 * i) = make_uint2(outw[0], outw[1]);
}

// ============================================================================
// Fused passBC. Tile: 192 out-cols x 8 out-rows, grid (11,128).
// blockDim = 224 = W_IN. smem 54KB + ~68 regs -> 4 blocks/SM (28 warps).
// ============================================================================
#define W_OUT 192
#define W_IN  224                  // + 2*RAD halo columns == blockDim
#define HB    8                    // output rows per block
#define CHC_F 8                    // outputs per horizontal-slider task
#define NCHK  (W_OUT / CHC_F)      // 24 chunks per row
#define NGRP  (W_IN / CHC_F)       // 28 column-groups
#define STRIDE_A (W_IN * 4 + 4)    // 900 words; %32==4 -> conflict-free
#define STRIDE_B (W_IN * 2 + 2)    // 450 words; %32==2 -> conflict-free
#define GRP_WORDS 12               // 10 h-words + fs + pad (48B)
#define SMEM_WORDS (HB * (STRIDE_A + STRIDE_B) + NGRP * HB * GRP_WORDS)
#define SMEM_BYTES (SMEM_WORDS * 4)   // 53952 B -> 4 blocks/SM
#define SENT 0x00130000u           // class 19, wpe payload 0

__device__ __forceinline__ void pk_add(unsigned long long& w0,
                                       unsigned long long& w1,
                                       unsigned& w2, int cls) {
    if (cls < 8)       w0 += 1ull << (cls * 8);
    else if (cls < 16) w1 += 1ull << ((cls & 7) * 8);
    else               w2 += 1u << ((cls - 16) * 8);   // cls 19 -> spare byte 3
}
__device__ __forceinline__ void pk_sub(unsigned long long& w0,
                                       unsigned long long& w1,
                                       unsigned& w2, int cls) {
    if (cls < 8)       w0 -= 1ull << (cls * 8);
    else if (cls < 16) w1 -= 1ull << ((cls & 7) * 8);
    else               w2 -= 1u << ((cls - 16) * 8);
}

// unpack 4 bytes into two u32 halfword pairs
#define PLO(w) __byte_perm((w), 0, 0x4140)
#define PHI(w) __byte_perm((w), 0, 0x4342)

__device__ __forceinline__ float h2f_lo(unsigned u) {
    return __half2float(__ushort_as_half((unsigned short)u));
}

__device__ __forceinline__ void apply_add(uint4 a, uint2 b,
                                          unsigned* h, float& fs) {
    h[0] += PLO(a.x); h[1] += PHI(a.x);
    h[2] += PLO(a.y); h[3] += PHI(a.y);
    h[4] += PLO(a.z); h[5] += PHI(a.z);
    h[6] += PLO(a.w); h[7] += PHI(a.w);
    h[8] += PLO(b.x); h[9] += PHI(b.x);
    fs += __uint_as_float(b.y);
}
__device__ __forceinline__ void apply_sub(uint4 a, uint2 b,
                                          unsigned* h, float& fs) {
    h[0] -= PLO(a.x); h[1] -= PHI(a.x);
    h[2] -= PLO(a.y); h[3] -= PHI(a.y);
    h[4] -= PLO(a.z); h[5] -= PHI(a.z);
    h[6] -= PLO(a.w); h[7] -= PHI(a.w);
    h[8] -= PLO(b.x); h[9] -= PHI(b.x);
    fs -= __uint_as_float(b.y);
}

// add one h-format group record (12 words) to accumulators
__device__ __forceinline__ void grp_add(const unsigned* __restrict__ g,
                                        unsigned* h, float& fs) {
    uint4 a = *(const uint4*)g;
    uint4 b = *(const uint4*)(g + 4);
    uint4 c = *(const uint4*)(g + 8);
    h[0] += a.x; h[1] += a.y; h[2] += a.z; h[3] += a.w;
    h[4] += b.x; h[5] += b.y; h[6] += b.z; h[7] += b.w;
    h[8] += c.x; h[9] += c.y;
    fs += __uint_as_float(c.z);
}

__global__ __launch_bounds__(W_IN, 4) void fusedBC(float* __restrict__ out) {
    extern __shared__ unsigned sm[];
    unsigned* smA = sm;                          // HB * STRIDE_A words
    unsigned* smB = sm + HB * STRIDE_A;          // HB * STRIDE_B words
    unsigned* smG = smB + HB * STRIDE_B;         // NGRP*HB*GRP_WORDS words
    const int x0 = blockIdx.x * W_OUT;
    const int y0 = blockIdx.y * HB;
    const int tid = threadIdx.x;

    // ------------- Phase 1: vertical 33-tap sliders, dual prime chains ------
    {
        int xg = x0 - RAD + tid;
        bool xv = (xg >= 0) && (xg < WW);
        int xc = min(max(xg, 0), WW - 1);        // safe address, value gated

        unsigned long long w0a = 0, w0b = 0, w1a = 0, w1b = 0;
        unsigned w2a = 0, w2b = 0;
        float fsa = 0.f, fsb = 0.f;
#pragma unroll
        for (int yi = 0; yi < 33; yi += 2) {     // even rows -> chain A
            int y = y0 - RAD + yi;
            bool inb = xv && (y >= 0) && (y < HH);
            unsigned u = inb ? g_packed[y * WW + xc] : SENT;
            fsa += h2f_lo(u);
            pk_add(w0a, w1a, w2a, (int)(u >> 16));
        }
#pragma unroll
        for (int yi = 1; yi < 33; yi += 2) {     // odd rows -> chain B
            int y = y0 - RAD + yi;
            bool inb = xv && (y >= 0) && (y < HH);
            unsigned u = inb ? g_packed[y * WW + xc] : SENT;
            fsb += h2f_lo(u);
            pk_add(w0b, w1b, w2b, (int)(u >> 16));
        }
        unsigned long long w0 = w0a + w0b, w1 = w1a + w1b;
        unsigned w2 = w2a + w2b;
        float fs = fsa + fsb;

        // batch all 16 slide words (MLP = 16)
        unsigned ua[HB], ud[HB];
#pragma unroll
        for (int r = 0; r < HB; r++) {
            int ya = y0 + r + RAD + 1;
            ua[r] = (xv && (ya < HH)) ? g_packed[ya * WW + xc] : SENT;
            int yr = y0 + r - RAD;
            ud[r] = (xv && (yr >= 0)) ? g_packed[yr * WW + xc] : SENT;
        }

#pragma unroll
        for (int r = 0; r < HB; r++) {
            *(uint4*)(smA + r * STRIDE_A + tid * 4) =
                make_uint4((unsigned)w0, (unsigned)(w0 >> 32),
                           (unsigned)w1, (unsigned)(w1 >> 32));
            *(uint2*)(smB + r * STRIDE_B + tid * 2) =
                make_uint2(w2, __float_as_uint(fs));
            fs += h2f_lo(ua[r]);
            pk_add(w0, w1, w2, (int)(ua[r] >> 16));
            fs -= h2f_lo(ud[r]);
            pk_sub(w0, w1, w2, (int)(ud[r] >> 16));
        }
    }
    __syncthreads();

    // ------------- Phase 1.5: 8-col group sums (224 tasks = 28g x 8r) -------
    {
        const int r = tid & 7;                   // low bits: conflict-free LDS
        const int g = tid >> 3;                  // 0..27
        const unsigned* rowA = smA + r * STRIDE_A;
        const unsigned* rowB = smB + r * STRIDE_B;

        unsigned h[10];
#pragma unroll
        for (int i = 0; i < 10; i++) h[i] = 0;
        float fs = 0.f;
#pragma unroll
        for (int k = 0; k < 8; k++) {
            int s = g * 8 + k;
            apply_add(*(const uint4*)(rowA + s * 4),
                      *(const uint2*)(rowB + s * 2), h, fs);
        }
        unsigned* dst = smG + (g * 8 + r) * GRP_WORDS;
        *(uint4*)dst       = make_uint4(h[0], h[1], h[2], h[3]);
        *(uint4*)(dst + 4) = make_uint4(h[4], h[5], h[6], h[7]);
        *(uint4*)(dst + 8) = make_uint4(h[8], h[9], __float_as_uint(fs), 0u);
    }
    __syncthreads();

    // ------------- Phase 2: horizontal sliders, software-pipelined ----------
    {
        const int r = tid & 7;      // low bits -> conflict-free LDS phases
        const int c = tid >> 3;     // 0..27; chunks >= NCHK idle
        const int xo = x0 + c * CHC_F;
        if (c < NCHK && xo < WW) {
            const unsigned* rowA = smA + r * STRIDE_A;
            const unsigned* rowB = smB + r * STRIDE_B;

            int yy = y0 + r;
            int wy = min(yy + RAD, HH - 1) - max(yy - RAD, 0) + 1;

            unsigned h[10];
#pragma unroll
            for (int i = 0; i < 10; i++) h[i] = 0;
            float fs = 0.f;

            // prime: groups c..c+3 cover records [8c, 8c+32), + record 8c+32
#pragma unroll
            for (int i = 0; i < 4; i++)
                grp_add(smG + ((c + i) * 8 + r) * GRP_WORDS, h, fs);
            {
                int s = c * CHC_F + 32;
                apply_add(*(const uint4*)(rowA + s * 4),
                          *(const uint2*)(rowB + s * 2), h, fs);
            }

            float s4[4], i4[4], u4[4];
#pragma unroll
            for (int k = 0; k < CHC_F; k++) {
                // ---- prefetch the incoming record BEFORE entropy ----
                uint4 aN; uint2 bN;
                if (k < CHC_F - 1) {
                    int sN = c * CHC_F + k + 33;
                    aN = *(const uint4*)(rowA + sN * 4);
                    bN = *(const uint2*)(rowB + sN * 2);
                }

                // ---- entropy of current window: 4 accumulator chains ----
                int x = xo + k;
                int wx = min(x + RAD, WW - 1) - max(x - RAD, 0) + 1;
                float fc = (float)(wx * wy);       // exact window size
                float invc = __frcp_rn(fc);
                float l2c  = __log2f(fc);

                float acc0 = 0.f, acc1 = 0.f, acc2 = 0.f, acc3 = 0.f;
#pragma unroll
                for (int p = 0; p < 10; p += 2) {  // even p: chains 0/1
                    float slo = (float)(h[p] & 0xFFFFu);
                    float shi = (float)(h[p] >> 16);
                    acc0 += slo * __log2f(fmaxf(slo, 1.f));
                    acc1 += shi * __log2f(fmaxf(shi, 1.f));
                }
#pragma unroll
                for (int p = 1; p < 10; p += 2) {  // odd p: chains 2/3
                    float slo = (float)(h[p] & 0xFFFFu);
                    acc2 += slo * __log2f(fmaxf(slo, 1.f));
                    if (p != 9) {                  // lane 19 is pad/sentinel
                        float shi = (float)(h[p] >> 16);
                        acc3 += shi * __log2f(fmaxf(shi, 1.f));
                    }
                }
                float acc = (acc0 + acc1) + (acc2 + acc3);
                float impurity = (l2c - acc * invc) * LOG2_TO_19;
                float unc = fs * invc;

                s4[k & 3] = impurity * unc;
                i4[k & 3] = impurity;
                u4[k & 3] = unc;

                if ((k & 3) == 3) {
                    int o = yy * WW + xo + (k & ~3);
                    *(float4*)(out + o)            = make_float4(s4[0], s4[1], s4[2], s4[3]);
                    *(float4*)(out + HWSZ + o)     = make_float4(i4[0], i4[1], i4[2], i4[3]);
                    *(float4*)(out + 2 * HWSZ + o) = make_float4(u4[0], u4[1], u4[2], u4[3]);
                }

                // ---- slide: prefetched add, direct-smem sub ----
                if (k < CHC_F - 1) {
                    apply_add(aN, bN, h, fs);
                    int sO = c * CHC_F + k;
                    apply_sub(*(const uint4*)(rowA + sO * 4),
                              *(const uint2*)(rowB + sO * 2), h, fs);
                }
            }
        }
    }
}

// ============================================================================
extern "C" void kernel_launch(void* const* d_in, const int* in_sizes, int n_in,
                              void* d_out, int out_size) {
    const float* logit = (const float*)d_in[0];
    const float* cw    = (const float*)d_in[1];
    float* out = (float*)d_out;

    cudaFuncSetAttribute(fusedBC, cudaFuncAttributeMaxDynamicSharedMemorySize,
                         SMEM_BYTES);

    passA<<<(HWSZ / 2 + 255) / 256, 256>>>((const float2*)logit, cw);
    fusedBC<<<dim3((WW + W_OUT - 1) / W_OUT, HH / HB), W_IN, SMEM_BYTES>>>(out);
}

// round 16
// speedup vs baseline: 1.0215x; 1.0215x over previous
#include <cuda_runtime.h>
#include <cuda_bf16.h>
#include <cuda_fp16.h>

#define HH 1024
#define WW 2048
#define HWSZ (HH * WW)
#define NC 19
#define RAD 16
#define INV_LOG19 0.3396224f      // 1 / ln(19)
#define LOG2_TO_19 0.23541016f    // ln(2) / ln(19)

// -------- scratch (device globals: allocation-free per harness rules) -------
// packed per-pixel record: bits[16:21) = argmax class, bits[0:16) = fp16 wpe
__device__ unsigned g_packed[HWSZ];

// ============================================================================
// Pass A: 2 pixels/thread via float2 loads (R14 version, measured best)
// ============================================================================
__global__ __launch_bounds__(256) void passA(const float2* __restrict__ logit2,
                                             const float* __restrict__ cw) {
    int i = blockIdx.x * blockDim.x + threadIdx.x;   // pair index
    if (i >= HWSZ / 2) return;

    float2 v[NC];
#pragma unroll
    for (int c = 0; c < NC; c++) v[c] = logit2[c * (HWSZ / 2) + i];

    unsigned outw[2];
#pragma unroll
    for (int l = 0; l < 2; l++) {
        float x[NC];
#pragma unroll
        for (int c = 0; c < NC; c++) x[c] = l ? v[c].y : v[c].x;

        float m = x[0];
        int am = 0;
#pragma unroll
        for (int c = 1; c < NC; c++) {
            if (x[c] > m) { m = x[c]; am = c; }
        }

        float S = 0.f, T = 0.f;
#pragma unroll
        for (int c = 0; c < NC; c++) {
            float d = x[c] - m;
            float e = __expf(d);
            S += e;
            T += e * d;
        }
        float ent = __logf(S) - T * __frcp_rn(S);
        float wpe = ent * cw[am] * INV_LOG19;

        outw[l] = ((unsigned)am << 16)
                | (unsigned)__half_as_ushort(__float2half_rn(wpe));
    }
    *(uint2*)(g_packed + 2 * i) = make_uint2(outw[0], outw[1]);
}

// ============================================================================
// Fused passBC. Tile: 192 out-cols x 8 out-rows, grid (11,128).
// blockDim = 224 = W_IN. smem 54KB -> 4 blocks/SM (28 warps).
// Entropy converts int lanes to float via exponent-bias trick (ALU+FMA)
// instead of I2F, relieving the shared XU/MUFU pipe.
// ============================================================================
#define W_OUT 192
#define W_IN  224                  // + 2*RAD halo columns == blockDim
#define HB    8                    // output rows per block
#define CHC_F 8                    // outputs per horizontal-slider task
#define NCHK  (W_OUT / CHC_F)      // 24 chunks per row
#define NGRP  (W_IN / CHC_F)       // 28 column-groups
#define STRIDE_A (W_IN * 4 + 4)    // 900 words; %32==4 -> conflict-free
#define STRIDE_B (W_IN * 2 + 2)    // 450 words; %32==2 -> conflict-free
#define GRP_WORDS 12               // 10 h-words + fs + pad (48B)
#define SMEM_WORDS (HB * (STRIDE_A + STRIDE_B) + NGRP * HB * GRP_WORDS)
#define SMEM_BYTES (SMEM_WORDS * 4)   // 53952 B -> 4 blocks/SM
#define SENT 0x00130000u           // class 19, wpe payload 0

// exact int->float for 0 <= s < 2^23 without the XU-pipe I2F
__device__ __forceinline__ float itof(unsigned s) {
    return __uint_as_float(0x4B000000u | s) - 8388608.f;
}

__device__ __forceinline__ void pk_add(unsigned long long& w0,
                                       unsigned long long& w1,
                                       unsigned& w2, int cls) {
    if (cls < 8)       w0 += 1ull << (cls * 8);
    else if (cls < 16) w1 += 1ull << ((cls & 7) * 8);
    else               w2 += 1u << ((cls - 16) * 8);   // cls 19 -> spare byte 3
}
__device__ __forceinline__ void pk_sub(unsigned long long& w0,
                                       unsigned long long& w1,
                                       unsigned& w2, int cls) {
    if (cls < 8)       w0 -= 1ull << (cls * 8);
    else if (cls < 16) w1 -= 1ull << ((cls & 7) * 8);
    else               w2 -= 1u << ((cls - 16) * 8);
}

// unpack 4 bytes into two u32 halfword pairs
#define PLO(w) __byte_perm((w), 0, 0x4140)
#define PHI(w) __byte_perm((w), 0, 0x4342)

__device__ __forceinline__ float h2f_lo(unsigned u) {
    return __half2float(__ushort_as_half((unsigned short)u));
}

__device__ __forceinline__ void apply_add(uint4 a, uint2 b,
                                          unsigned* h, float& fs) {
    h[0] += PLO(a.x); h[1] += PHI(a.x);
    h[2] += PLO(a.y); h[3] += PHI(a.y);
    h[4] += PLO(a.z); h[5] += PHI(a.z);
    h[6] += PLO(a.w); h[7] += PHI(a.w);
    h[8] += PLO(b.x); h[9] += PHI(b.x);
    fs += __uint_as_float(b.y);
}
__device__ __forceinline__ void apply_sub(uint4 a, uint2 b,
                                          unsigned* h, float& fs) {
    h[0] -= PLO(a.x); h[1] -= PHI(a.x);
    h[2] -= PLO(a.y); h[3] -= PHI(a.y);
    h[4] -= PLO(a.z); h[5] -= PHI(a.z);
    h[6] -= PLO(a.w); h[7] -= PHI(a.w);
    h[8] -= PLO(b.x); h[9] -= PHI(b.x);
    fs -= __uint_as_float(b.y);
}

// add one h-format group record (12 words) to accumulators
__device__ __forceinline__ void grp_add(const unsigned* __restrict__ g,
                                        unsigned* h, float& fs) {
    uint4 a = *(const uint4*)g;
    uint4 b = *(const uint4*)(g + 4);
    uint4 c = *(const uint4*)(g + 8);
    h[0] += a.x; h[1] += a.y; h[2] += a.z; h[3] += a.w;
    h[4] += b.x; h[5] += b.y; h[6] += b.z; h[7] += b.w;
    h[8] += c.x; h[9] += c.y;
    fs += __uint_as_float(c.z);
}

__global__ __launch_bounds__(W_IN, 4) void fusedBC(float* __restrict__ out) {
    extern __shared__ unsigned sm[];
    unsigned* smA = sm;                          // HB * STRIDE_A words
    unsigned* smB = sm + HB * STRIDE_A;          // HB * STRIDE_B words
    unsigned* smG = smB + HB * STRIDE_B;         // NGRP*HB*GRP_WORDS words
    const int x0 = blockIdx.x * W_OUT;
    const int y0 = blockIdx.y * HB;
    const int tid = threadIdx.x;

    // ------------- Phase 1: vertical 33-tap sliders, dual prime chains ------
    {
        int xg = x0 - RAD + tid;
        bool xv = (xg >= 0) && (xg < WW);
        int xc = min(max(xg, 0), WW - 1);        // safe address, value gated

        unsigned long long w0a = 0, w0b = 0, w1a = 0, w1b = 0;
        unsigned w2a = 0, w2b = 0;
        float fsa = 0.f, fsb = 0.f;
#pragma unroll
        for (int yi = 0; yi < 33; yi += 2) {     // even rows -> chain A
            int y = y0 - RAD + yi;
            bool inb = xv && (y >= 0) && (y < HH);
            unsigned u = inb ? g_packed[y * WW + xc] : SENT;
            fsa += h2f_lo(u);
            pk_add(w0a, w1a, w2a, (int)(u >> 16));
        }
#pragma unroll
        for (int yi = 1; yi < 33; yi += 2) {     // odd rows -> chain B
            int y = y0 - RAD + yi;
            bool inb = xv && (y >= 0) && (y < HH);
            unsigned u = inb ? g_packed[y * WW + xc] : SENT;
            fsb += h2f_lo(u);
            pk_add(w0b, w1b, w2b, (int)(u >> 16));
        }
        unsigned long long w0 = w0a + w0b, w1 = w1a + w1b;
        unsigned w2 = w2a + w2b;
        float fs = fsa + fsb;

        // batch all 16 slide words (MLP = 16)
        unsigned ua[HB], ud[HB];
#pragma unroll
        for (int r = 0; r < HB; r++) {
            int ya = y0 + r + RAD + 1;
            ua[r] = (xv && (ya < HH)) ? g_packed[ya * WW + xc] : SENT;
            int yr = y0 + r - RAD;
            ud[r] = (xv && (yr >= 0)) ? g_packed[yr * WW + xc] : SENT;
        }

#pragma unroll
        for (int r = 0; r < HB; r++) {
            *(uint4*)(smA + r * STRIDE_A + tid * 4) =
                make_uint4((unsigned)w0, (unsigned)(w0 >> 32),
                           (unsigned)w1, (unsigned)(w1 >> 32));
            *(uint2*)(smB + r * STRIDE_B + tid * 2) =
                make_uint2(w2, __float_as_uint(fs));
            fs += h2f_lo(ua[r]);
            pk_add(w0, w1, w2, (int)(ua[r] >> 16));
            fs -= h2f_lo(ud[r]);
            pk_sub(w0, w1, w2, (int)(ud[r] >> 16));
        }
    }
    __syncthreads();

    // ------------- Phase 1.5: 8-col group sums (224 tasks = 28g x 8r) -------
    {
        const int r = tid & 7;                   // low bits: conflict-free LDS
        const int g = tid >> 3;                  // 0..27
        const unsigned* rowA = smA + r * STRIDE_A;
        const unsigned* rowB = smB + r * STRIDE_B;

        unsigned h[10];
#pragma unroll
        for (int i = 0; i < 10; i++) h[i] = 0;
        float fs = 0.f;
#pragma unroll
        for (int k = 0; k < 8; k++) {
            int s = g * 8 + k;
            apply_add(*(const uint4*)(rowA + s * 4),
                      *(const uint2*)(rowB + s * 2), h, fs);
        }
        unsigned* dst = smG + (g * 8 + r) * GRP_WORDS;
        *(uint4*)dst       = make_uint4(h[0], h[1], h[2], h[3]);
        *(uint4*)(dst + 4) = make_uint4(h[4], h[5], h[6], h[7]);
        *(uint4*)(dst + 8) = make_uint4(h[8], h[9], __float_as_uint(fs), 0u);
    }
    __syncthreads();

    // ------------- Phase 2: horizontal sliders, software-pipelined ----------
    {
        const int r = tid & 7;      // low bits -> conflict-free LDS phases
        const int c = tid >> 3;     // 0..27; chunks >= NCHK idle
        const int xo = x0 + c * CHC_F;
        if (c < NCHK && xo < WW) {
            const unsigned* rowA = smA + r * STRIDE_A;
            const unsigned* rowB = smB + r * STRIDE_B;

            int yy = y0 + r;
            int wy = min(yy + RAD, HH - 1) - max(yy - RAD, 0) + 1;

            unsigned h[10];
#pragma unroll
            for (int i = 0; i < 10; i++) h[i] = 0;
            float fs = 0.f;

            // prime: groups c..c+3 cover records [8c, 8c+32), + record 8c+32
#pragma unroll
            for (int i = 0; i < 4; i++)
                grp_add(smG + ((c + i) * 8 + r) * GRP_WORDS, h, fs);
            {
                int s = c * CHC_F + 32;
                apply_add(*(const uint4*)(rowA + s * 4),
                          *(const uint2*)(rowB + s * 2), h, fs);
            }

            float s4[4], i4[4], u4[4];
#pragma unroll
            for (int k = 0; k < CHC_F; k++) {
                // ---- prefetch the incoming record BEFORE entropy ----
                uint4 aN; uint2 bN;
                if (k < CHC_F - 1) {
                    int sN = c * CHC_F + k + 33;
                    aN = *(const uint4*)(rowA + sN * 4);
                    bN = *(const uint2*)(rowB + sN * 2);
                }

                // ---- entropy of current window (no I2F: itof bit trick) ----
                int x = xo + k;
                int wx = min(x + RAD, WW - 1) - max(x - RAD, 0) + 1;
                float fc = itof((unsigned)(wx * wy));  // exact window size
                float invc = __frcp_rn(fc);
                float l2c  = __log2f(fc);

                float acc0 = 0.f, acc1 = 0.f, acc2 = 0.f, acc3 = 0.f;
#pragma unroll
                for (int p = 0; p < 10; p += 2) {  // even p: chains 0/1
                    float slo = itof(h[p] & 0xFFFFu);
                    float shi = itof(h[p] >> 16);
                    acc0 += slo * __log2f(fmaxf(slo, 1.f));
                    acc1 += shi * __log2f(fmaxf(shi, 1.f));
                }
#pragma unroll
                for (int p = 1; p < 10; p += 2) {  // odd p: chains 2/3
                    float slo = itof(h[p] & 0xFFFFu);
                    acc2 += slo * __log2f(fmaxf(slo, 1.f));
                    if (p != 9) {                  // lane 19 is pad/sentinel
                        float shi = itof(h[p] >> 16);
                        acc3 += shi * __log2f(fmaxf(shi, 1.f));
                    }
                }
                float acc = (acc0 + acc1) + (acc2 + acc3);
                float impurity = (l2c - acc * invc) * LOG2_TO_19;
                float unc = fs * invc;

                s4[k & 3] = impurity * unc;
                i4[k & 3] = impurity;
                u4[k & 3] = unc;

                if ((k & 3) == 3) {
                    int o = yy * WW + xo + (k & ~3);
                    *(float4*)(out + o)            = make_float4(s4[0], s4[1], s4[2], s4[3]);
                    *(float4*)(out + HWSZ + o)     = make_float4(i4[0], i4[1], i4[2], i4[3]);
                    *(float4*)(out + 2 * HWSZ + o) = make_float4(u4[0], u4[1], u4[2], u4[3]);
                }

                // ---- slide: prefetched add, direct-smem sub ----
                if (k < CHC_F - 1) {
                    apply_add(aN, bN, h, fs);
                    int sO = c * CHC_F + k;
                    apply_sub(*(const uint4*)(rowA + sO * 4),
                              *(const uint2*)(rowB + sO * 2), h, fs);
                }
            }
        }
    }
}

// ============================================================================
extern "C" void kernel_launch(void* const* d_in, const int* in_sizes, int n_in,
                              void* d_out, int out_size) {
    const float* logit = (const float*)d_in[0];
    const float* cw    = (const float*)d_in[1];
    float* out = (float*)d_out;

    cudaFuncSetAttribute(fusedBC, cudaFuncAttributeMaxDynamicSharedMemorySize,
                         SMEM_BYTES);

    passA<<<(HWSZ / 2 + 255) / 256, 256>>>((const float2*)logit, cw);
    fusedBC<<<dim3((WW + W_OUT - 1) / W_OUT, HH / HB), W_IN, SMEM_BYTES>>>(out);
}

// round 17
// speedup vs baseline: 1.0281x; 1.0065x over previous
#include <cuda_runtime.h>
#include <cuda_bf16.h>
#include <cuda_fp16.h>

#define HH 1024
#define WW 2048
#define HWSZ (HH * WW)
#define NC 19
#define RAD 16
#define INV_LOG19 0.3396224f      // 1 / ln(19)
#define LOG2_TO_19 0.23541016f    // ln(2) / ln(19)

// -------- scratch (device globals: allocation-free per harness rules) -------
// packed per-pixel record: bits[16:21) = argmax class, bits[0:16) = fp16 wpe
__device__ unsigned g_packed[HWSZ];

// ============================================================================
// Pass A: 2 pixels/thread via float2 loads (R14 version, measured best)
// ============================================================================
__global__ __launch_bounds__(256) void passA(const float2* __restrict__ logit2,
                                             const float* __restrict__ cw) {
    int i = blockIdx.x * blockDim.x + threadIdx.x;   // pair index
    if (i >= HWSZ / 2) return;

    float2 v[NC];
#pragma unroll
    for (int c = 0; c < NC; c++) v[c] = logit2[c * (HWSZ / 2) + i];

    unsigned outw[2];
#pragma unroll
    for (int l = 0; l < 2; l++) {
        float x[NC];
#pragma unroll
        for (int c = 0; c < NC; c++) x[c] = l ? v[c].y : v[c].x;

        float m = x[0];
        int am = 0;
#pragma unroll
        for (int c = 1; c < NC; c++) {
            if (x[c] > m) { m = x[c]; am = c; }
        }

        float S = 0.f, T = 0.f;
#pragma unroll
        for (int c = 0; c < NC; c++) {
            float d = x[c] - m;
            float e = __expf(d);
            S += e;
            T += e * d;
        }
        float ent = __logf(S) - T * __frcp_rn(S);
        float wpe = ent * cw[am] * INV_LOG19;

        outw[l] = ((unsigned)am << 16)
                | (unsigned)__half_as_ushort(__float2half_rn(wpe));
    }
    *(uint2*)(g_packed + 2 * i) = make_uint2(outw[0], outw[1]);
}

// ============================================================================
// Fused passBC. Tile: 192 out-cols x 8 out-rows, grid (11,128).
// blockDim = 224 = W_IN. smem 54KB -> 4 blocks/SM (28 warps).
// (R15 body: 4-chain entropy with plain I2F — measured best at 55.9us)
// ============================================================================
#define W_OUT 192
#define W_IN  224                  // + 2*RAD halo columns == blockDim
#define HB    8                    // output rows per block
#define CHC_F 8                    // outputs per horizontal-slider task
#define NCHK  (W_OUT / CHC_F)      // 24 chunks per row
#define NGRP  (W_IN / CHC_F)       // 28 column-groups
#define STRIDE_A (W_IN * 4 + 4)    // 900 words; %32==4 -> conflict-free
#define STRIDE_B (W_IN * 2 + 2)    // 450 words; %32==2 -> conflict-free
#define GRP_WORDS 12               // 10 h-words + fs + pad (48B)
#define SMEM_WORDS (HB * (STRIDE_A + STRIDE_B) + NGRP * HB * GRP_WORDS)
#define SMEM_BYTES (SMEM_WORDS * 4)   // 53952 B -> 4 blocks/SM
#define SENT 0x00130000u           // class 19, wpe payload 0

__device__ __forceinline__ void pk_add(unsigned long long& w0,
                                       unsigned long long& w1,
                                       unsigned& w2, int cls) {
    if (cls < 8)       w0 += 1ull << (cls * 8);
    else if (cls < 16) w1 += 1ull << ((cls & 7) * 8);
    else               w2 += 1u << ((cls - 16) * 8);   // cls 19 -> spare byte 3
}
__device__ __forceinline__ void pk_sub(unsigned long long& w0,
                                       unsigned long long& w1,
                                       unsigned& w2, int cls) {
    if (cls < 8)       w0 -= 1ull << (cls * 8);
    else if (cls < 16) w1 -= 1ull << ((cls & 7) * 8);
    else               w2 -= 1u << ((cls - 16) * 8);
}

// unpack 4 bytes into two u32 halfword pairs
#define PLO(w) __byte_perm((w), 0, 0x4140)
#define PHI(w) __byte_perm((w), 0, 0x4342)

__device__ __forceinline__ float h2f_lo(unsigned u) {
    return __half2float(__ushort_as_half((unsigned short)u));
}

__device__ __forceinline__ void apply_add(uint4 a, uint2 b,
                                          unsigned* h, float& fs) {
    h[0] += PLO(a.x); h[1] += PHI(a.x);
    h[2] += PLO(a.y); h[3] += PHI(a.y);
    h[4] += PLO(a.z); h[5] += PHI(a.z);
    h[6] += PLO(a.w); h[7] += PHI(a.w);
    h[8] += PLO(b.x); h[9] += PHI(b.x);
    fs += __uint_as_float(b.y);
}
__device__ __forceinline__ void apply_sub(uint4 a, uint2 b,
                                          unsigned* h, float& fs) {
    h[0] -= PLO(a.x); h[1] -= PHI(a.x);
    h[2] -= PLO(a.y); h[3] -= PHI(a.y);
    h[4] -= PLO(a.z); h[5] -= PHI(a.z);
    h[6] -= PLO(a.w); h[7] -= PHI(a.w);
    h[8] -= PLO(b.x); h[9] -= PHI(b.x);
    fs -= __uint_as_float(b.y);
}

// add one h-format group record (12 words) to accumulators
__device__ __forceinline__ void grp_add(const unsigned* __restrict__ g,
                                        unsigned* h, float& fs) {
    uint4 a = *(const uint4*)g;
    uint4 b = *(const uint4*)(g + 4);
    uint4 c = *(const uint4*)(g + 8);
    h[0] += a.x; h[1] += a.y; h[2] += a.z; h[3] += a.w;
    h[4] += b.x; h[5] += b.y; h[6] += b.z; h[7] += b.w;
    h[8] += c.x; h[9] += c.y;
    fs += __uint_as_float(c.z);
}

__global__ __launch_bounds__(W_IN, 4) void fusedBC(float* __restrict__ out) {
    extern __shared__ unsigned sm[];
    unsigned* smA = sm;                          // HB * STRIDE_A words
    unsigned* smB = sm + HB * STRIDE_A;          // HB * STRIDE_B words
    unsigned* smG = smB + HB * STRIDE_B;         // NGRP*HB*GRP_WORDS words
    const int x0 = blockIdx.x * W_OUT;
    const int y0 = blockIdx.y * HB;
    const int tid = threadIdx.x;

    // ------------- Phase 1: vertical 33-tap sliders, dual prime chains ------
    {
        int xg = x0 - RAD + tid;
        bool xv = (xg >= 0) && (xg < WW);
        int xc = min(max(xg, 0), WW - 1);        // safe address, value gated

        unsigned long long w0a = 0, w0b = 0, w1a = 0, w1b = 0;
        unsigned w2a = 0, w2b = 0;
        float fsa = 0.f, fsb = 0.f;
#pragma unroll
        for (int yi = 0; yi < 33; yi += 2) {     // even rows -> chain A
            int y = y0 - RAD + yi;
            bool inb = xv && (y >= 0) && (y < HH);
            unsigned u = inb ? g_packed[y * WW + xc] : SENT;
            fsa += h2f_lo(u);
            pk_add(w0a, w1a, w2a, (int)(u >> 16));
        }
#pragma unroll
        for (int yi = 1; yi < 33; yi += 2) {     // odd rows -> chain B
            int y = y0 - RAD + yi;
            bool inb = xv && (y >= 0) && (y < HH);
            unsigned u = inb ? g_packed[y * WW + xc] : SENT;
            fsb += h2f_lo(u);
            pk_add(w0b, w1b, w2b, (int)(u >> 16));
        }
        unsigned long long w0 = w0a + w0b, w1 = w1a + w1b;
        unsigned w2 = w2a + w2b;
        float fs = fsa + fsb;

        // batch all 16 slide words (MLP = 16)
        unsigned ua[HB], ud[HB];
#pragma unroll
        for (int r = 0; r < HB; r++) {
            int ya = y0 + r + RAD + 1;
            ua[r] = (xv && (ya < HH)) ? g_packed[ya * WW + xc] : SENT;
            int yr = y0 + r - RAD;
            ud[r] = (xv && (yr >= 0)) ? g_packed[yr * WW + xc] : SENT;
        }

#pragma unroll
        for (int r = 0; r < HB; r++) {
            *(uint4*)(smA + r * STRIDE_A + tid * 4) =
                make_uint4((unsigned)w0, (unsigned)(w0 >> 32),
                           (unsigned)w1, (unsigned)(w1 >> 32));
            *(uint2*)(smB + r * STRIDE_B + tid * 2) =
                make_uint2(w2, __float_as_uint(fs));
            fs += h2f_lo(ua[r]);
            pk_add(w0, w1, w2, (int)(ua[r] >> 16));
            fs -= h2f_lo(ud[r]);
            pk_sub(w0, w1, w2, (int)(ud[r] >> 16));
        }
    }
    __syncthreads();

    // ------------- Phase 1.5: 8-col group sums (224 tasks = 28g x 8r) -------
    {
        const int r = tid & 7;                   // low bits: conflict-free LDS
        const int g = tid >> 3;                  // 0..27
        const unsigned* rowA = smA + r * STRIDE_A;
        const unsigned* rowB = smB + r * STRIDE_B;

        unsigned h[10];
#pragma unroll
        for (int i = 0; i < 10; i++) h[i] = 0;
        float fs = 0.f;
#pragma unroll
        for (int k = 0; k < 8; k++) {
            int s = g * 8 + k;
            apply_add(*(const uint4*)(rowA + s * 4),
                      *(const uint2*)(rowB + s * 2), h, fs);
        }
        unsigned* dst = smG + (g * 8 + r) * GRP_WORDS;
        *(uint4*)dst       = make_uint4(h[0], h[1], h[2], h[3]);
        *(uint4*)(dst + 4) = make_uint4(h[4], h[5], h[6], h[7]);
        *(uint4*)(dst + 8) = make_uint4(h[8], h[9], __float_as_uint(fs), 0u);
    }
    __syncthreads();

    // ------------- Phase 2: horizontal sliders, software-pipelined ----------
    {
        const int r = tid & 7;      // low bits -> conflict-free LDS phases
        const int c = tid >> 3;     // 0..27; chunks >= NCHK idle
        const int xo = x0 + c * CHC_F;
        if (c < NCHK && xo < WW) {
            const unsigned* rowA = smA + r * STRIDE_A;
            const unsigned* rowB = smB + r * STRIDE_B;

            int yy = y0 + r;
            int wy = min(yy + RAD, HH - 1) - max(yy - RAD, 0) + 1;

            unsigned h[10];
#pragma unroll
            for (int i = 0; i < 10; i++) h[i] = 0;
            float fs = 0.f;

            // prime: groups c..c+3 cover records [8c, 8c+32), + record 8c+32
#pragma unroll
            for (int i = 0; i < 4; i++)
                grp_add(smG + ((c + i) * 8 + r) * GRP_WORDS, h, fs);
            {
                int s = c * CHC_F + 32;
                apply_add(*(const uint4*)(rowA + s * 4),
                          *(const uint2*)(rowB + s * 2), h, fs);
            }

            float s4[4], i4[4], u4[4];
#pragma unroll
            for (int k = 0; k < CHC_F; k++) {
                // ---- prefetch the incoming record BEFORE entropy ----
                uint4 aN; uint2 bN;
                if (k < CHC_F - 1) {
                    int sN = c * CHC_F + k + 33;
                    aN = *(const uint4*)(rowA + sN * 4);
                    bN = *(const uint2*)(rowB + sN * 2);
                }

                // ---- entropy of current window: 4 accumulator chains ----
                int x = xo + k;
                int wx = min(x + RAD, WW - 1) - max(x - RAD, 0) + 1;
                float fc = (float)(wx * wy);       // exact window size
                float invc = __frcp_rn(fc);
                float l2c  = __log2f(fc);

                float acc0 = 0.f, acc1 = 0.f, acc2 = 0.f, acc3 = 0.f;
#pragma unroll
                for (int p = 0; p < 10; p += 2) {  // even p: chains 0/1
                    float slo = (float)(h[p] & 0xFFFFu);
                    float shi = (float)(h[p] >> 16);
                    acc0 += slo * __log2f(fmaxf(slo, 1.f));
                    acc1 += shi * __log2f(fmaxf(shi, 1.f));
                }
#pragma unroll
                for (int p = 1; p < 10; p += 2) {  // odd p: chains 2/3
                    float slo = (float)(h[p] & 0xFFFFu);
                    acc2 += slo * __log2f(fmaxf(slo, 1.f));
                    if (p != 9) {                  // lane 19 is pad/sentinel
                        float shi = (float)(h[p] >> 16);
                        acc3 += shi * __log2f(fmaxf(shi, 1.f));
                    }
                }
                float acc = (acc0 + acc1) + (acc2 + acc3);
                float impurity = (l2c - acc * invc) * LOG2_TO_19;
                float unc = fs * invc;

                s4[k & 3] = impurity * unc;
                i4[k & 3] = impurity;
                u4[k & 3] = unc;

                if ((k & 3) == 3) {
                    int o = yy * WW + xo + (k & ~3);
                    *(float4*)(out + o)            = make_float4(s4[0], s4[1], s4[2], s4[3]);
                    *(float4*)(out + HWSZ + o)     = make_float4(i4[0], i4[1], i4[2], i4[3]);
                    *(float4*)(out + 2 * HWSZ + o) = make_float4(u4[0], u4[1], u4[2], u4[3]);
                }

                // ---- slide: prefetched add, direct-smem sub ----
                if (k < CHC_F - 1) {
                    apply_add(aN, bN, h, fs);
                    int sO = c * CHC_F + k;
                    apply_sub(*(const uint4*)(rowA + sO * 4),
                              *(const uint2*)(rowB + sO * 2), h, fs);
                }
            }
        }
    }
}

// ============================================================================
extern "C" void kernel_launch(void* const* d_in, const int* in_sizes, int n_in,
                              void* d_out, int out_size) {
    const float* logit = (const float*)d_in[0];
    const float* cw    = (const float*)d_in[1];
    float* out = (float*)d_out;

    cudaFuncSetAttribute(fusedBC, cudaFuncAttributeMaxDynamicSharedMemorySize,
                         SMEM_BYTES);

    passA<<<(HWSZ / 2 + 255) / 256, 256>>>((const float2*)logit, cw);
    fusedBC<<<dim3((WW + W_OUT - 1) / W_OUT, HH / HB), W_IN, SMEM_BYTES>>>(out);
}